// round 6
// baseline (speedup 1.0000x reference)
#include <cuda_runtime.h>
#include <cuda_bf16.h>

// LSTM_24936580121326 R6: 2 elements/thread (halves per-element LDS),
// X staged in dynamic smem (coalesced), unit-interleaved gate rows so
// activations fuse into the gate loop (4 live accs/elem), tanh.approx
// with sigmoid 0.5-fold in staged weights.

#define T_STEPS 49
#define EPB 512   // elements per block (256 threads x 2)

__device__ __forceinline__ float tanhf_hw(float x) {
    float y; asm("tanh.approx.f32 %0, %1;" : "=f"(y) : "f"(x)); return y;
}
__device__ __forceinline__ float sig_folded(float zh) {   // z arrives pre-halved
    return fmaf(0.5f, tanhf_hw(zh), 0.5f);
}

__global__ void __launch_bounds__(256) lstm_fused_kernel(
    const float* __restrict__ X,
    const float* __restrict__ W_ih0, const float* __restrict__ W_hh0,
    const float* __restrict__ b_ih0, const float* __restrict__ b_hh0,
    const float* __restrict__ W_ih1, const float* __restrict__ W_hh1,
    const float* __restrict__ b_ih1, const float* __restrict__ b_hh1,
    const float* __restrict__ W_lin, const float* __restrict__ b_lin,
    float* __restrict__ out, int Bn)
{
    extern __shared__ float s_x[];          // [EPB][49]

    // Unit-interleaved rows: r = 4u+gi maps to source gate row (u + 8*gi),
    // gi: 0=i 1=f 2=g 3=o. i/f/o rows scaled 0.5 (sigmoid fold).
    __shared__ float4 s_whh0[64];   // [32 rows][8] as 2x float4
    __shared__ float4 s_wih1[64];
    __shared__ float4 s_whh1[64];
    __shared__ float4 s_wx0[8];     // W_ih0, unit-major packed (4 gates)
    __shared__ float4 s_bb0[8];     // biases layer1, unit-major
    __shared__ float4 s_bb1[8];     // biases layer2
    __shared__ float  s_wlin[8];
    __shared__ float  s_blin;

    int tid = threadIdx.x;
    {
        int r = tid >> 3, j = tid & 7;
        int u = r >> 2, gi = r & 3;
        float sc = (gi == 2) ? 1.0f : 0.5f;
        int src = (u + 8 * gi) * 8 + j;
        ((float*)s_whh0)[r * 8 + j] = sc * W_hh0[src];
        ((float*)s_wih1)[r * 8 + j] = sc * W_ih1[src];
        ((float*)s_whh1)[r * 8 + j] = sc * W_hh1[src];
    }
    if (tid < 32) {
        int u = tid >> 2, gi = tid & 3;
        float sc = (gi == 2) ? 1.0f : 0.5f;
        int src = u + 8 * gi;
        ((float*)s_wx0)[tid] = sc * W_ih0[src];
        ((float*)s_bb0)[tid] = sc * (b_ih0[src] + b_hh0[src]);
        ((float*)s_bb1)[tid] = sc * (b_ih1[src] + b_hh1[src]);
    }
    if (tid < 8)  s_wlin[tid] = W_lin[tid];
    if (tid == 0) s_blin = b_lin[0];

    // ---- stage X for this block (coalesced) ----
    int base = blockIdx.x * EPB;
    int count = Bn - base; if (count > EPB) count = EPB;
    for (int i = tid; i < count * T_STEPS; i += 256)
        s_x[i] = X[(size_t)base * T_STEPS + i];
    __syncthreads();

    int eA = tid, eB = tid + 256;            // local element indices
    bool vA = eA < count, vB = eB < count;

    float h1A[8], c1A[8], h2A[8], c2A[8];
    float h1B[8], c1B[8], h2B[8], c2B[8];
#pragma unroll
    for (int u = 0; u < 8; ++u) {
        h1A[u] = c1A[u] = h2A[u] = c2A[u] = 0.f;
        h1B[u] = c1B[u] = h2B[u] = c2B[u] = 0.f;
    }

#pragma unroll 1
    for (int t = 0; t < T_STEPS; ++t) {
        float xA = vA ? s_x[eA * T_STEPS + t] : 0.f;
        float xB = vB ? s_x[eB * T_STEPS + t] : 0.f;

        float h1nA[8], h1nB[8];
        // ---------- layer 1 ----------
#pragma unroll
        for (int u = 0; u < 8; ++u) {
            float4 wx = s_wx0[u];
            float4 bb = s_bb0[u];
            float aiA = fmaf(wx.x, xA, bb.x), afA = fmaf(wx.y, xA, bb.y);
            float agA = fmaf(wx.z, xA, bb.z), aoA = fmaf(wx.w, xA, bb.w);
            float aiB = fmaf(wx.x, xB, bb.x), afB = fmaf(wx.y, xB, bb.y);
            float agB = fmaf(wx.z, xB, bb.z), aoB = fmaf(wx.w, xB, bb.w);
#pragma unroll
            for (int gi = 0; gi < 4; ++gi) {
                float4 w0 = s_whh0[2 * (4 * u + gi)];
                float4 w1 = s_whh0[2 * (4 * u + gi) + 1];
                float aA, aB;
                aA = fmaf(w0.x, h1A[0], 0.f); // replaced below; keep chains tight
                aA = fmaf(w0.x, h1A[0],
                     fmaf(w0.y, h1A[1],
                     fmaf(w0.z, h1A[2],
                     fmaf(w0.w, h1A[3],
                     fmaf(w1.x, h1A[4],
                     fmaf(w1.y, h1A[5],
                     fmaf(w1.z, h1A[6],
                     fmaf(w1.w, h1A[7], 0.f))))))));
                aB = fmaf(w0.x, h1B[0],
                     fmaf(w0.y, h1B[1],
                     fmaf(w0.z, h1B[2],
                     fmaf(w0.w, h1B[3],
                     fmaf(w1.x, h1B[4],
                     fmaf(w1.y, h1B[5],
                     fmaf(w1.z, h1B[6],
                     fmaf(w1.w, h1B[7], 0.f))))))));
                if (gi == 0) { aiA += aA; aiB += aB; }
                else if (gi == 1) { afA += aA; afB += aB; }
                else if (gi == 2) { agA += aA; agB += aB; }
                else { aoA += aA; aoB += aB; }
            }
            {
                float ig = sig_folded(aiA), fg = sig_folded(afA);
                float gg = tanhf_hw(agA), og = sig_folded(aoA);
                c1A[u] = fmaf(fg, c1A[u], ig * gg);
                h1nA[u] = og * tanhf_hw(c1A[u]);
            }
            {
                float ig = sig_folded(aiB), fg = sig_folded(afB);
                float gg = tanhf_hw(agB), og = sig_folded(aoB);
                c1B[u] = fmaf(fg, c1B[u], ig * gg);
                h1nB[u] = og * tanhf_hw(c1B[u]);
            }
        }

        float h2nA[8], h2nB[8];
        // ---------- layer 2 ----------
#pragma unroll
        for (int u = 0; u < 8; ++u) {
            float4 bb = s_bb1[u];
            float aiA = bb.x, afA = bb.y, agA = bb.z, aoA = bb.w;
            float aiB = bb.x, afB = bb.y, agB = bb.z, aoB = bb.w;
#pragma unroll
            for (int gi = 0; gi < 4; ++gi) {
                float4 u0 = s_wih1[2 * (4 * u + gi)];
                float4 u1 = s_wih1[2 * (4 * u + gi) + 1];
                float4 v0 = s_whh1[2 * (4 * u + gi)];
                float4 v1 = s_whh1[2 * (4 * u + gi) + 1];
                float aA =
                     fmaf(u0.x, h1nA[0],
                     fmaf(u0.y, h1nA[1],
                     fmaf(u0.z, h1nA[2],
                     fmaf(u0.w, h1nA[3],
                     fmaf(u1.x, h1nA[4],
                     fmaf(u1.y, h1nA[5],
                     fmaf(u1.z, h1nA[6],
                     fmaf(u1.w, h1nA[7],
                     fmaf(v0.x, h2A[0],
                     fmaf(v0.y, h2A[1],
                     fmaf(v0.z, h2A[2],
                     fmaf(v0.w, h2A[3],
                     fmaf(v1.x, h2A[4],
                     fmaf(v1.y, h2A[5],
                     fmaf(v1.z, h2A[6],
                     fmaf(v1.w, h2A[7], 0.f))))))))))))))));
                float aB =
                     fmaf(u0.x, h1nB[0],
                     fmaf(u0.y, h1nB[1],
                     fmaf(u0.z, h1nB[2],
                     fmaf(u0.w, h1nB[3],
                     fmaf(u1.x, h1nB[4],
                     fmaf(u1.y, h1nB[5],
                     fmaf(u1.z, h1nB[6],
                     fmaf(u1.w, h1nB[7],
                     fmaf(v0.x, h2B[0],
                     fmaf(v0.y, h2B[1],
                     fmaf(v0.z, h2B[2],
                     fmaf(v0.w, h2B[3],
                     fmaf(v1.x, h2B[4],
                     fmaf(v1.y, h2B[5],
                     fmaf(v1.z, h2B[6],
                     fmaf(v1.w, h2B[7], 0.f))))))))))))))));
                if (gi == 0) { aiA += aA; aiB += aB; }
                else if (gi == 1) { afA += aA; afB += aB; }
                else if (gi == 2) { agA += aA; agB += aB; }
                else { aoA += aA; aoB += aB; }
            }
            {
                float ig = sig_folded(aiA), fg = sig_folded(afA);
                float gg = tanhf_hw(agA), og = sig_folded(aoA);
                c2A[u] = fmaf(fg, c2A[u], ig * gg);
                h2nA[u] = og * tanhf_hw(c2A[u]);
            }
            {
                float ig = sig_folded(aiB), fg = sig_folded(afB);
                float gg = tanhf_hw(agB), og = sig_folded(aoB);
                c2B[u] = fmaf(fg, c2B[u], ig * gg);
                h2nB[u] = og * tanhf_hw(c2B[u]);
            }
        }

#pragma unroll
        for (int u = 0; u < 8; ++u) {
            h1A[u] = h1nA[u]; h2A[u] = h2nA[u];
            h1B[u] = h1nB[u]; h2B[u] = h2nB[u];
        }
    }

    // ---------- relu -> linear -> relu ----------
    float accA = s_blin, accB = s_blin;
#pragma unroll
    for (int u = 0; u < 8; ++u) {
        accA = fmaf(s_wlin[u], fmaxf(h2A[u], 0.0f), accA);
        accB = fmaf(s_wlin[u], fmaxf(h2B[u], 0.0f), accB);
    }
    if (vA) out[base + eA] = fmaxf(accA, 0.0f);
    if (vB) out[base + eB] = fmaxf(accB, 0.0f);
}

extern "C" void kernel_launch(void* const* d_in, const int* in_sizes, int n_in,
                              void* d_out, int out_size) {
    const float* X     = (const float*)d_in[0];
    const float* W_ih0 = (const float*)d_in[1];
    const float* W_hh0 = (const float*)d_in[2];
    const float* b_ih0 = (const float*)d_in[3];
    const float* b_hh0 = (const float*)d_in[4];
    const float* W_ih1 = (const float*)d_in[5];
    const float* W_hh1 = (const float*)d_in[6];
    const float* b_ih1 = (const float*)d_in[7];
    const float* b_hh1 = (const float*)d_in[8];
    const float* W_lin = (const float*)d_in[9];
    const float* b_lin = (const float*)d_in[10];

    int Bn = out_size;
    int smem = EPB * T_STEPS * (int)sizeof(float);   // 100352 B
    cudaFuncSetAttribute(lstm_fused_kernel,
                         cudaFuncAttributeMaxDynamicSharedMemorySize, smem);
    int blocks = (Bn + EPB - 1) / EPB;
    lstm_fused_kernel<<<blocks, 256, smem>>>(
        X, W_ih0, W_hh0, b_ih0, b_hh0,
        W_ih1, W_hh1, b_ih1, b_hh1,
        W_lin, b_lin, (float*)d_out, Bn);
}

// round 7
// speedup vs baseline: 11.3813x; 11.3813x over previous
#include <cuda_runtime.h>
#include <cuda_bf16.h>

// LSTM_24936580121326 R7: R5 structure (proven regs=112, 417us) with weights
// moved from shared memory to __constant__ (uniform-datapath LDCU, bypasses
// L1/LSU which was the 71.8% binder). Preproc kernel scales/reorders weights
// into a device scratch; capturable D2D memcpy promotes them to constant.

#define T_STEPS 49

struct WPack {
    float4 whh0[64];   // [32 gates][8] scaled rows as 2x float4
    float4 wih1[64];
    float4 whh1[64];
    float  wih0[32];   // layer0 input weights (scaled)
    float  b0[32];     // (b_ih0 + b_hh0) scaled
    float  b1[32];     // (b_ih1 + b_hh1) scaled
    float  wlin[8];
    float  blin;
};

__device__   WPack g_wtmp;   // staging scratch (written by preproc kernel)
__constant__ WPack c_w;      // uniform-datapath weights

__device__ __forceinline__ float tanhf_hw(float x) {
    float y; asm("tanh.approx.f32 %0, %1;" : "=f"(y) : "f"(x)); return y;
}
__device__ __forceinline__ float sig_folded(float zh) {   // z arrives pre-halved
    return fmaf(0.5f, tanhf_hw(zh), 0.5f);
}
__device__ __forceinline__ float gate_scale(int k) {
    return (k >= 16 && k < 24) ? 1.0f : 0.5f;   // i/f/o: 0.5 ; g: 1.0
}

// ---------------- preproc: scale + pre-add biases into g_wtmp ----------------
__global__ void prep_weights_kernel(
    const float* __restrict__ W_ih0, const float* __restrict__ W_hh0,
    const float* __restrict__ b_ih0, const float* __restrict__ b_hh0,
    const float* __restrict__ W_ih1, const float* __restrict__ W_hh1,
    const float* __restrict__ b_ih1, const float* __restrict__ b_hh1,
    const float* __restrict__ W_lin, const float* __restrict__ b_lin)
{
    int tid = threadIdx.x;
    if (tid < 256) {
        float sc = gate_scale(tid >> 3);
        ((float*)g_wtmp.whh0)[tid] = sc * W_hh0[tid];
        ((float*)g_wtmp.wih1)[tid] = sc * W_ih1[tid];
        ((float*)g_wtmp.whh1)[tid] = sc * W_hh1[tid];
    }
    if (tid < 32) {
        float sc = gate_scale(tid);
        g_wtmp.wih0[tid] = sc * W_ih0[tid];
        g_wtmp.b0[tid]   = sc * (b_ih0[tid] + b_hh0[tid]);
        g_wtmp.b1[tid]   = sc * (b_ih1[tid] + b_hh1[tid]);
    }
    if (tid < 8)  g_wtmp.wlin[tid] = W_lin[tid];
    if (tid == 0) g_wtmp.blin = b_lin[0];
}

// ---------------- fused LSTM (weights from constant) ----------------
__global__ void __launch_bounds__(256) lstm_fused_kernel(
    const float* __restrict__ X, float* __restrict__ out, int Bn)
{
    int b = blockIdx.x * blockDim.x + threadIdx.x;
    if (b >= Bn) return;

    float h1[8], c1[8], h2[8], c2[8];
#pragma unroll
    for (int u = 0; u < 8; ++u) { h1[u] = 0.f; c1[u] = 0.f; h2[u] = 0.f; c2[u] = 0.f; }

    const float* __restrict__ xp = X + (long long)b * T_STEPS;

    for (int t = 0; t < T_STEPS; ++t) {
        float x = __ldg(xp + t);
        float g[32];

        // ---------- layer 1: gates (rows pre-scaled) ----------
#pragma unroll
        for (int k = 0; k < 32; ++k) {
            float4 wa = c_w.whh0[2 * k];
            float4 wb = c_w.whh0[2 * k + 1];
            float a = fmaf(c_w.wih0[k], x, c_w.b0[k]);
            a = fmaf(wa.x, h1[0], a);
            a = fmaf(wa.y, h1[1], a);
            a = fmaf(wa.z, h1[2], a);
            a = fmaf(wa.w, h1[3], a);
            a = fmaf(wb.x, h1[4], a);
            a = fmaf(wb.y, h1[5], a);
            a = fmaf(wb.z, h1[6], a);
            a = fmaf(wb.w, h1[7], a);
            g[k] = a;
        }
#pragma unroll
        for (int u = 0; u < 8; ++u) {
            float ig = sig_folded(g[u]);
            float fg = sig_folded(g[u + 8]);
            float gg = tanhf_hw(g[u + 16]);
            float og = sig_folded(g[u + 24]);
            c1[u] = fmaf(fg, c1[u], ig * gg);
            h1[u] = og * tanhf_hw(c1[u]);
        }

        // ---------- layer 2 ----------
#pragma unroll
        for (int k = 0; k < 32; ++k) {
            float4 ua = c_w.wih1[2 * k];
            float4 ub = c_w.wih1[2 * k + 1];
            float4 va = c_w.whh1[2 * k];
            float4 vb = c_w.whh1[2 * k + 1];
            float a = c_w.b1[k];
            a = fmaf(ua.x, h1[0], a);
            a = fmaf(ua.y, h1[1], a);
            a = fmaf(ua.z, h1[2], a);
            a = fmaf(ua.w, h1[3], a);
            a = fmaf(ub.x, h1[4], a);
            a = fmaf(ub.y, h1[5], a);
            a = fmaf(ub.z, h1[6], a);
            a = fmaf(ub.w, h1[7], a);
            a = fmaf(va.x, h2[0], a);
            a = fmaf(va.y, h2[1], a);
            a = fmaf(va.z, h2[2], a);
            a = fmaf(va.w, h2[3], a);
            a = fmaf(vb.x, h2[4], a);
            a = fmaf(vb.y, h2[5], a);
            a = fmaf(vb.z, h2[6], a);
            a = fmaf(vb.w, h2[7], a);
            g[k] = a;
        }
#pragma unroll
        for (int u = 0; u < 8; ++u) {
            float ig = sig_folded(g[u]);
            float fg = sig_folded(g[u + 8]);
            float gg = tanhf_hw(g[u + 16]);
            float og = sig_folded(g[u + 24]);
            c2[u] = fmaf(fg, c2[u], ig * gg);
            h2[u] = og * tanhf_hw(c2[u]);
        }
    }

    // ---------- relu -> linear -> relu ----------
    float acc = c_w.blin;
#pragma unroll
    for (int u = 0; u < 8; ++u)
        acc = fmaf(c_w.wlin[u], fmaxf(h2[u], 0.0f), acc);
    out[b] = fmaxf(acc, 0.0f);
}

extern "C" void kernel_launch(void* const* d_in, const int* in_sizes, int n_in,
                              void* d_out, int out_size) {
    const float* X     = (const float*)d_in[0];
    const float* W_ih0 = (const float*)d_in[1];
    const float* W_hh0 = (const float*)d_in[2];
    const float* b_ih0 = (const float*)d_in[3];
    const float* b_hh0 = (const float*)d_in[4];
    const float* W_ih1 = (const float*)d_in[5];
    const float* W_hh1 = (const float*)d_in[6];
    const float* b_ih1 = (const float*)d_in[7];
    const float* b_hh1 = (const float*)d_in[8];
    const float* W_lin = (const float*)d_in[9];
    const float* b_lin = (const float*)d_in[10];

    int Bn = out_size;

    prep_weights_kernel<<<1, 256>>>(
        W_ih0, W_hh0, b_ih0, b_hh0,
        W_ih1, W_hh1, b_ih1, b_hh1, W_lin, b_lin);

    // Promote staged weights to constant memory (D2D memcpy node; capturable).
    void* src = nullptr;
    cudaGetSymbolAddress(&src, g_wtmp);
    cudaMemcpyToSymbolAsync(c_w, src, sizeof(WPack), 0,
                            cudaMemcpyDeviceToDevice, 0);

    int threads = 256;
    int blocks = (Bn + threads - 1) / threads;
    lstm_fused_kernel<<<blocks, threads>>>(X, (float*)d_out, Bn);
}

// round 8
// speedup vs baseline: 12.6972x; 1.1156x over previous
#include <cuda_runtime.h>
#include <cuda_bf16.h>

// LSTM_24936580121326 R8: R7 shell (constant weights, 256-thr, lb(256)) with
// gate matvecs in packed fma.rn.f32x2 — 2 gates per instruction, unit-major
// (i,f)/(g,o) pairing so only 2 packed accumulators are live per unit.

#define T_STEPS 49

typedef unsigned long long u64;

struct WPack {
    // [8 units][4 q][2 pairs] ; each ulonglong2 = pairs for cols 2q, 2q+1
    ulonglong2 w1if[8][4];   // layer1 W_hh rows (i,f) scaled 0.5
    ulonglong2 w1go[8][4];   // layer1 W_hh rows (g unscaled, o 0.5)
    ulonglong2 w2uif[8][4];  // layer2 W_ih
    ulonglong2 w2ugo[8][4];
    ulonglong2 w2vif[8][4];  // layer2 W_hh
    ulonglong2 w2vgo[8][4];
    u64 wx_if[8], wx_go[8];  // layer1 W_ih (input dim 1)
    u64 b1if[8], b1go[8];
    u64 b2if[8], b2go[8];
    float wlin[8];
    float blin;
};

__device__   WPack g_wtmp;
__constant__ WPack c_w;

__device__ __forceinline__ u64 pack2(float lo, float hi) {
    u64 r; asm("mov.b64 %0, {%1, %2};" : "=l"(r) : "f"(lo), "f"(hi)); return r;
}
__device__ __forceinline__ void unpack2(u64 v, float& lo, float& hi) {
    asm("mov.b64 {%0, %1}, %2;" : "=f"(lo), "=f"(hi) : "l"(v));
}
__device__ __forceinline__ u64 fma2(u64 a, u64 b, u64 c) {
    u64 d; asm("fma.rn.f32x2 %0, %1, %2, %3;" : "=l"(d) : "l"(a), "l"(b), "l"(c)); return d;
}
__device__ __forceinline__ float tanhf_hw(float x) {
    float y; asm("tanh.approx.f32 %0, %1;" : "=f"(y) : "f"(x)); return y;
}
__device__ __forceinline__ float sig_folded(float zh) {   // pre-halved input
    return fmaf(0.5f, tanhf_hw(zh), 0.5f);
}

// ---------------- preproc ----------------
__global__ void prep_weights_kernel(
    const float* __restrict__ W_ih0, const float* __restrict__ W_hh0,
    const float* __restrict__ b_ih0, const float* __restrict__ b_hh0,
    const float* __restrict__ W_ih1, const float* __restrict__ W_hh1,
    const float* __restrict__ b_ih1, const float* __restrict__ b_hh1,
    const float* __restrict__ W_lin, const float* __restrict__ b_lin)
{
    int tid = threadIdx.x;
    if (tid < 128) {
        int u = tid >> 4, q = (tid >> 2) & 3, s = tid & 3;
        int col = 2 * q + (s >> 1);
        int sel = s & 1;                 // 0 -> first gate of pair, 1 -> second
        int idx = (u * 4 + q) * 4 + s;   // float index within the array
        int gIF = u + 8 * sel;           // i or f
        int gGO = u + 16 + 8 * sel;      // g or o
        float scGO = sel ? 0.5f : 1.0f;  // g unscaled, o 0.5
        ((float*)g_wtmp.w1if)[idx]  = 0.5f * W_hh0[gIF * 8 + col];
        ((float*)g_wtmp.w1go)[idx]  = scGO * W_hh0[gGO * 8 + col];
        ((float*)g_wtmp.w2uif)[idx] = 0.5f * W_ih1[gIF * 8 + col];
        ((float*)g_wtmp.w2ugo)[idx] = scGO * W_ih1[gGO * 8 + col];
        ((float*)g_wtmp.w2vif)[idx] = 0.5f * W_hh1[gIF * 8 + col];
        ((float*)g_wtmp.w2vgo)[idx] = scGO * W_hh1[gGO * 8 + col];
    }
    if (tid < 8) {
        int u = tid;
        float* p;
        p = (float*)g_wtmp.wx_if; p[2*u] = 0.5f * W_ih0[u];      p[2*u+1] = 0.5f * W_ih0[u+8];
        p = (float*)g_wtmp.wx_go; p[2*u] =        W_ih0[u+16];   p[2*u+1] = 0.5f * W_ih0[u+24];
        p = (float*)g_wtmp.b1if;  p[2*u] = 0.5f*(b_ih0[u]+b_hh0[u]);
                                  p[2*u+1] = 0.5f*(b_ih0[u+8]+b_hh0[u+8]);
        p = (float*)g_wtmp.b1go;  p[2*u] =       (b_ih0[u+16]+b_hh0[u+16]);
                                  p[2*u+1] = 0.5f*(b_ih0[u+24]+b_hh0[u+24]);
        p = (float*)g_wtmp.b2if;  p[2*u] = 0.5f*(b_ih1[u]+b_hh1[u]);
                                  p[2*u+1] = 0.5f*(b_ih1[u+8]+b_hh1[u+8]);
        p = (float*)g_wtmp.b2go;  p[2*u] =       (b_ih1[u+16]+b_hh1[u+16]);
                                  p[2*u+1] = 0.5f*(b_ih1[u+24]+b_hh1[u+24]);
        g_wtmp.wlin[u] = W_lin[u];
    }
    if (tid == 0) g_wtmp.blin = b_lin[0];
}

// ---------------- fused LSTM ----------------
__global__ void __launch_bounds__(256) lstm_fused_kernel(
    const float* __restrict__ X, float* __restrict__ out, int Bn)
{
    int b = blockIdx.x * blockDim.x + threadIdx.x;
    if (b >= Bn) return;

    u64 hp1[8], hp2[8];     // {h,h} broadcast packs
    float c1[8], c2[8];
    u64 zero = pack2(0.f, 0.f);
#pragma unroll
    for (int u = 0; u < 8; ++u) { hp1[u] = zero; hp2[u] = zero; c1[u] = 0.f; c2[u] = 0.f; }

    const float* __restrict__ xp = X + (long long)b * T_STEPS;

    for (int t = 0; t < T_STEPS; ++t) {
        float x = __ldg(xp + t);
        u64 xx = pack2(x, x);

        // ---------- layer 1 ----------
        u64 hn1[8];
#pragma unroll
        for (int u = 0; u < 8; ++u) {
            u64 aif = fma2(c_w.wx_if[u], xx, c_w.b1if[u]);
            u64 ago = fma2(c_w.wx_go[u], xx, c_w.b1go[u]);
#pragma unroll
            for (int q = 0; q < 4; ++q) {
                ulonglong2 wi = c_w.w1if[u][q];
                ulonglong2 wg = c_w.w1go[u][q];
                aif = fma2(wi.x, hp1[2*q],   aif);
                aif = fma2(wi.y, hp1[2*q+1], aif);
                ago = fma2(wg.x, hp1[2*q],   ago);
                ago = fma2(wg.y, hp1[2*q+1], ago);
            }
            float zi, zf, zg, zo;
            unpack2(aif, zi, zf);
            unpack2(ago, zg, zo);
            float ig = sig_folded(zi), fg = sig_folded(zf);
            float gg = tanhf_hw(zg),  og = sig_folded(zo);
            c1[u] = fmaf(fg, c1[u], ig * gg);
            float h = og * tanhf_hw(c1[u]);
            hn1[u] = pack2(h, h);
        }

        // ---------- layer 2 ----------
        u64 hn2[8];
#pragma unroll
        for (int u = 0; u < 8; ++u) {
            u64 aif = c_w.b2if[u];
            u64 ago = c_w.b2go[u];
#pragma unroll
            for (int q = 0; q < 4; ++q) {
                ulonglong2 ui = c_w.w2uif[u][q];
                ulonglong2 ug = c_w.w2ugo[u][q];
                aif = fma2(ui.x, hn1[2*q],   aif);
                aif = fma2(ui.y, hn1[2*q+1], aif);
                ago = fma2(ug.x, hn1[2*q],   ago);
                ago = fma2(ug.y, hn1[2*q+1], ago);
            }
#pragma unroll
            for (int q = 0; q < 4; ++q) {
                ulonglong2 vi = c_w.w2vif[u][q];
                ulonglong2 vg = c_w.w2vgo[u][q];
                aif = fma2(vi.x, hp2[2*q],   aif);
                aif = fma2(vi.y, hp2[2*q+1], aif);
                ago = fma2(vg.x, hp2[2*q],   ago);
                ago = fma2(vg.y, hp2[2*q+1], ago);
            }
            float zi, zf, zg, zo;
            unpack2(aif, zi, zf);
            unpack2(ago, zg, zo);
            float ig = sig_folded(zi), fg = sig_folded(zf);
            float gg = tanhf_hw(zg),  og = sig_folded(zo);
            c2[u] = fmaf(fg, c2[u], ig * gg);
            float h = og * tanhf_hw(c2[u]);
            hn2[u] = pack2(h, h);
        }

#pragma unroll
        for (int u = 0; u < 8; ++u) { hp1[u] = hn1[u]; hp2[u] = hn2[u]; }
    }

    // ---------- relu -> linear -> relu ----------
    float acc = c_w.blin;
#pragma unroll
    for (int u = 0; u < 8; ++u) {
        float h, d;
        unpack2(hp2[u], h, d);
        acc = fmaf(c_w.wlin[u], fmaxf(h, 0.0f), acc);
    }
    out[b] = fmaxf(acc, 0.0f);
}

extern "C" void kernel_launch(void* const* d_in, const int* in_sizes, int n_in,
                              void* d_out, int out_size) {
    const float* X     = (const float*)d_in[0];
    const float* W_ih0 = (const float*)d_in[1];
    const float* W_hh0 = (const float*)d_in[2];
    const float* b_ih0 = (const float*)d_in[3];
    const float* b_hh0 = (const float*)d_in[4];
    const float* W_ih1 = (const float*)d_in[5];
    const float* W_hh1 = (const float*)d_in[6];
    const float* b_ih1 = (const float*)d_in[7];
    const float* b_hh1 = (const float*)d_in[8];
    const float* W_lin = (const float*)d_in[9];
    const float* b_lin = (const float*)d_in[10];

    int Bn = out_size;

    prep_weights_kernel<<<1, 256>>>(
        W_ih0, W_hh0, b_ih0, b_hh0,
        W_ih1, W_hh1, b_ih1, b_hh1, W_lin, b_lin);

    void* src = nullptr;
    cudaGetSymbolAddress(&src, g_wtmp);
    cudaMemcpyToSymbolAsync(c_w, src, sizeof(WPack), 0,
                            cudaMemcpyDeviceToDevice, 0);

    int threads = 256;
    int blocks = (Bn + threads - 1) / threads;
    lstm_fused_kernel<<<blocks, threads>>>(X, (float*)d_out, Bn);
}

// round 9
// speedup vs baseline: 13.4212x; 1.0570x over previous
#include <cuda_runtime.h>
#include <cuda_bf16.h>

// LSTM_24936580121326 R9: R8 (constant-weight f32x2) + 2 batch elements per
// thread so every uniform weight load (LDCU) is amortized over 2 elements.
// Same per-unit fused-activation structure, packed {h,h} state per element.

#define T_STEPS 49

typedef unsigned long long u64;

struct WPack {
    ulonglong2 w1if[8][4];   // layer1 W_hh rows (i,f) scaled 0.5
    ulonglong2 w1go[8][4];   // layer1 W_hh rows (g unscaled, o 0.5)
    ulonglong2 w2uif[8][4];  // layer2 W_ih
    ulonglong2 w2ugo[8][4];
    ulonglong2 w2vif[8][4];  // layer2 W_hh
    ulonglong2 w2vgo[8][4];
    u64 wx_if[8], wx_go[8];  // layer1 W_ih (input dim 1)
    u64 b1if[8], b1go[8];
    u64 b2if[8], b2go[8];
    float wlin[8];
    float blin;
};

__device__   WPack g_wtmp;
__constant__ WPack c_w;

__device__ __forceinline__ u64 pack2(float lo, float hi) {
    u64 r; asm("mov.b64 %0, {%1, %2};" : "=l"(r) : "f"(lo), "f"(hi)); return r;
}
__device__ __forceinline__ void unpack2(u64 v, float& lo, float& hi) {
    asm("mov.b64 {%0, %1}, %2;" : "=f"(lo), "=f"(hi) : "l"(v));
}
__device__ __forceinline__ u64 fma2(u64 a, u64 b, u64 c) {
    u64 d; asm("fma.rn.f32x2 %0, %1, %2, %3;" : "=l"(d) : "l"(a), "l"(b), "l"(c)); return d;
}
__device__ __forceinline__ float tanhf_hw(float x) {
    float y; asm("tanh.approx.f32 %0, %1;" : "=f"(y) : "f"(x)); return y;
}
__device__ __forceinline__ float sig_folded(float zh) {   // pre-halved input
    return fmaf(0.5f, tanhf_hw(zh), 0.5f);
}

// ---------------- preproc ----------------
__global__ void prep_weights_kernel(
    const float* __restrict__ W_ih0, const float* __restrict__ W_hh0,
    const float* __restrict__ b_ih0, const float* __restrict__ b_hh0,
    const float* __restrict__ W_ih1, const float* __restrict__ W_hh1,
    const float* __restrict__ b_ih1, const float* __restrict__ b_hh1,
    const float* __restrict__ W_lin, const float* __restrict__ b_lin)
{
    int tid = threadIdx.x;
    if (tid < 128) {
        int u = tid >> 4, q = (tid >> 2) & 3, s = tid & 3;
        int col = 2 * q + (s >> 1);
        int sel = s & 1;
        int idx = (u * 4 + q) * 4 + s;
        int gIF = u + 8 * sel;           // i or f
        int gGO = u + 16 + 8 * sel;      // g or o
        float scGO = sel ? 0.5f : 1.0f;
        ((float*)g_wtmp.w1if)[idx]  = 0.5f * W_hh0[gIF * 8 + col];
        ((float*)g_wtmp.w1go)[idx]  = scGO * W_hh0[gGO * 8 + col];
        ((float*)g_wtmp.w2uif)[idx] = 0.5f * W_ih1[gIF * 8 + col];
        ((float*)g_wtmp.w2ugo)[idx] = scGO * W_ih1[gGO * 8 + col];
        ((float*)g_wtmp.w2vif)[idx] = 0.5f * W_hh1[gIF * 8 + col];
        ((float*)g_wtmp.w2vgo)[idx] = scGO * W_hh1[gGO * 8 + col];
    }
    if (tid < 8) {
        int u = tid;
        float* p;
        p = (float*)g_wtmp.wx_if; p[2*u] = 0.5f * W_ih0[u];      p[2*u+1] = 0.5f * W_ih0[u+8];
        p = (float*)g_wtmp.wx_go; p[2*u] =        W_ih0[u+16];   p[2*u+1] = 0.5f * W_ih0[u+24];
        p = (float*)g_wtmp.b1if;  p[2*u] = 0.5f*(b_ih0[u]+b_hh0[u]);
                                  p[2*u+1] = 0.5f*(b_ih0[u+8]+b_hh0[u+8]);
        p = (float*)g_wtmp.b1go;  p[2*u] =       (b_ih0[u+16]+b_hh0[u+16]);
                                  p[2*u+1] = 0.5f*(b_ih0[u+24]+b_hh0[u+24]);
        p = (float*)g_wtmp.b2if;  p[2*u] = 0.5f*(b_ih1[u]+b_hh1[u]);
                                  p[2*u+1] = 0.5f*(b_ih1[u+8]+b_hh1[u+8]);
        p = (float*)g_wtmp.b2go;  p[2*u] =       (b_ih1[u+16]+b_hh1[u+16]);
                                  p[2*u+1] = 0.5f*(b_ih1[u+24]+b_hh1[u+24]);
        g_wtmp.wlin[u] = W_lin[u];
    }
    if (tid == 0) g_wtmp.blin = b_lin[0];
}

// ---------------- fused LSTM: 2 elements per thread ----------------
__global__ void __launch_bounds__(256) lstm_fused_kernel(
    const float* __restrict__ X, float* __restrict__ out, int Bn)
{
    int tid  = threadIdx.x;
    int base = blockIdx.x * 512;
    int bA = base + tid;
    int bB = base + tid + 256;
    bool vA = bA < Bn, vB = bB < Bn;

    u64 hp1A[8], hp2A[8], hp1B[8], hp2B[8];
    float c1A[8], c2A[8], c1B[8], c2B[8];
    u64 zero = pack2(0.f, 0.f);
#pragma unroll
    for (int u = 0; u < 8; ++u) {
        hp1A[u] = hp2A[u] = hp1B[u] = hp2B[u] = zero;
        c1A[u] = c2A[u] = c1B[u] = c2B[u] = 0.f;
    }

    const float* __restrict__ xpA = X + (long long)(vA ? bA : 0) * T_STEPS;
    const float* __restrict__ xpB = X + (long long)(vB ? bB : 0) * T_STEPS;

    for (int t = 0; t < T_STEPS; ++t) {
        float xA = __ldg(xpA + t);
        float xB = __ldg(xpB + t);
        u64 xxA = pack2(xA, xA);
        u64 xxB = pack2(xB, xB);

        // ---------- layer 1 ----------
        u64 hn1A[8], hn1B[8];
#pragma unroll
        for (int u = 0; u < 8; ++u) {
            u64 wxi = c_w.wx_if[u], wxg = c_w.wx_go[u];
            u64 bi  = c_w.b1if[u],  bg  = c_w.b1go[u];
            u64 aifA = fma2(wxi, xxA, bi);
            u64 agoA = fma2(wxg, xxA, bg);
            u64 aifB = fma2(wxi, xxB, bi);
            u64 agoB = fma2(wxg, xxB, bg);
#pragma unroll
            for (int q = 0; q < 4; ++q) {
                ulonglong2 wi = c_w.w1if[u][q];
                ulonglong2 wg = c_w.w1go[u][q];
                aifA = fma2(wi.x, hp1A[2*q],   aifA);
                aifA = fma2(wi.y, hp1A[2*q+1], aifA);
                agoA = fma2(wg.x, hp1A[2*q],   agoA);
                agoA = fma2(wg.y, hp1A[2*q+1], agoA);
                aifB = fma2(wi.x, hp1B[2*q],   aifB);
                aifB = fma2(wi.y, hp1B[2*q+1], aifB);
                agoB = fma2(wg.x, hp1B[2*q],   agoB);
                agoB = fma2(wg.y, hp1B[2*q+1], agoB);
            }
            {
                float zi, zf, zg, zo;
                unpack2(aifA, zi, zf);
                unpack2(agoA, zg, zo);
                float ig = sig_folded(zi), fg = sig_folded(zf);
                float gg = tanhf_hw(zg),  og = sig_folded(zo);
                c1A[u] = fmaf(fg, c1A[u], ig * gg);
                float h = og * tanhf_hw(c1A[u]);
                hn1A[u] = pack2(h, h);
            }
            {
                float zi, zf, zg, zo;
                unpack2(aifB, zi, zf);
                unpack2(agoB, zg, zo);
                float ig = sig_folded(zi), fg = sig_folded(zf);
                float gg = tanhf_hw(zg),  og = sig_folded(zo);
                c1B[u] = fmaf(fg, c1B[u], ig * gg);
                float h = og * tanhf_hw(c1B[u]);
                hn1B[u] = pack2(h, h);
            }
        }

        // ---------- layer 2 ----------
        u64 hn2A[8], hn2B[8];
#pragma unroll
        for (int u = 0; u < 8; ++u) {
            u64 bi = c_w.b2if[u], bg = c_w.b2go[u];
            u64 aifA = bi, agoA = bg, aifB = bi, agoB = bg;
#pragma unroll
            for (int q = 0; q < 4; ++q) {
                ulonglong2 ui = c_w.w2uif[u][q];
                ulonglong2 ug = c_w.w2ugo[u][q];
                aifA = fma2(ui.x, hn1A[2*q],   aifA);
                aifA = fma2(ui.y, hn1A[2*q+1], aifA);
                agoA = fma2(ug.x, hn1A[2*q],   agoA);
                agoA = fma2(ug.y, hn1A[2*q+1], agoA);
                aifB = fma2(ui.x, hn1B[2*q],   aifB);
                aifB = fma2(ui.y, hn1B[2*q+1], aifB);
                agoB = fma2(ug.x, hn1B[2*q],   agoB);
                agoB = fma2(ug.y, hn1B[2*q+1], agoB);
            }
#pragma unroll
            for (int q = 0; q < 4; ++q) {
                ulonglong2 vi = c_w.w2vif[u][q];
                ulonglong2 vg = c_w.w2vgo[u][q];
                aifA = fma2(vi.x, hp2A[2*q],   aifA);
                aifA = fma2(vi.y, hp2A[2*q+1], aifA);
                agoA = fma2(vg.x, hp2A[2*q],   agoA);
                agoA = fma2(vg.y, hp2A[2*q+1], agoA);
                aifB = fma2(vi.x, hp2B[2*q],   aifB);
                aifB = fma2(vi.y, hp2B[2*q+1], aifB);
                agoB = fma2(vg.x, hp2B[2*q],   agoB);
                agoB = fma2(vg.y, hp2B[2*q+1], agoB);
            }
            {
                float zi, zf, zg, zo;
                unpack2(aifA, zi, zf);
                unpack2(agoA, zg, zo);
                float ig = sig_folded(zi), fg = sig_folded(zf);
                float gg = tanhf_hw(zg),  og = sig_folded(zo);
                c2A[u] = fmaf(fg, c2A[u], ig * gg);
                float h = og * tanhf_hw(c2A[u]);
                hn2A[u] = pack2(h, h);
            }
            {
                float zi, zf, zg, zo;
                unpack2(aifB, zi, zf);
                unpack2(agoB, zg, zo);
                float ig = sig_folded(zi), fg = sig_folded(zf);
                float gg = tanhf_hw(zg),  og = sig_folded(zo);
                c2B[u] = fmaf(fg, c2B[u], ig * gg);
                float h = og * tanhf_hw(c2B[u]);
                hn2B[u] = pack2(h, h);
            }
        }

#pragma unroll
        for (int u = 0; u < 8; ++u) {
            hp1A[u] = hn1A[u]; hp2A[u] = hn2A[u];
            hp1B[u] = hn1B[u]; hp2B[u] = hn2B[u];
        }
    }

    // ---------- relu -> linear -> relu ----------
    float accA = c_w.blin, accB = c_w.blin;
#pragma unroll
    for (int u = 0; u < 8; ++u) {
        float hA, hB, d;
        unpack2(hp2A[u], hA, d);
        unpack2(hp2B[u], hB, d);
        accA = fmaf(c_w.wlin[u], fmaxf(hA, 0.0f), accA);
        accB = fmaf(c_w.wlin[u], fmaxf(hB, 0.0f), accB);
    }
    if (vA) out[bA] = fmaxf(accA, 0.0f);
    if (vB) out[bB] = fmaxf(accB, 0.0f);
}

extern "C" void kernel_launch(void* const* d_in, const int* in_sizes, int n_in,
                              void* d_out, int out_size) {
    const float* X     = (const float*)d_in[0];
    const float* W_ih0 = (const float*)d_in[1];
    const float* W_hh0 = (const float*)d_in[2];
    const float* b_ih0 = (const float*)d_in[3];
    const float* b_hh0 = (const float*)d_in[4];
    const float* W_ih1 = (const float*)d_in[5];
    const float* W_hh1 = (const float*)d_in[6];
    const float* b_ih1 = (const float*)d_in[7];
    const float* b_hh1 = (const float*)d_in[8];
    const float* W_lin = (const float*)d_in[9];
    const float* b_lin = (const float*)d_in[10];

    int Bn = out_size;

    prep_weights_kernel<<<1, 256>>>(
        W_ih0, W_hh0, b_ih0, b_hh0,
        W_ih1, W_hh1, b_ih1, b_hh1, W_lin, b_lin);

    void* src = nullptr;
    cudaGetSymbolAddress(&src, g_wtmp);
    cudaMemcpyToSymbolAsync(c_w, src, sizeof(WPack), 0,
                            cudaMemcpyDeviceToDevice, 0);

    int blocks = (Bn + 511) / 512;
    lstm_fused_kernel<<<blocks, 256>>>(X, (float*)d_out, Bn);
}